// round 7
// baseline (speedup 1.0000x reference)
#include <cuda_runtime.h>
#include <cuda_bf16.h>
#include <cstdint>
#include <cstddef>

#define B_    16
#define N_    2048
#define FIN   256
#define FOUT  128
#define MTOT  (B_ * N_)
#define JC    64
#define NCH   (N_ / JC)

// ---------------- device scratch (no allocation allowed) ----------------
__device__ float g_h[(size_t)MTOT * FOUT];                 // 16 MB
__device__ float g_f1[MTOT];
__device__ float g_f2[MTOT];
__device__ __nv_bfloat16 g_hT_hi[(size_t)B_ * FOUT * N_];  // 8 MB  [b][f][n]
__device__ __nv_bfloat16 g_hT_lo[(size_t)B_ * FOUT * N_];  // 8 MB

// ---------------- PTX helpers (sm_80-compatible only) ----------------
__device__ __forceinline__ uint32_t smem_u32(const void* p) {
    uint32_t a;
    asm("{ .reg .u64 t; cvta.to.shared.u64 t, %1; cvt.u32.u64 %0, t; }"
        : "=r"(a) : "l"(p));
    return a;
}
__device__ __forceinline__ void ldsm_x4(uint32_t* r, uint32_t a) {
    asm volatile("ldmatrix.sync.aligned.m8n8.x4.shared.b16 {%0,%1,%2,%3}, [%4];"
                 : "=r"(r[0]), "=r"(r[1]), "=r"(r[2]), "=r"(r[3]) : "r"(a));
}
__device__ __forceinline__ void mma16816(float* d, const uint32_t* a,
                                         const uint32_t* b) {
    asm volatile(
        "mma.sync.aligned.m16n8k16.row.col.f32.bf16.bf16.f32 "
        "{%0,%1,%2,%3}, {%4,%5,%6,%7}, {%8,%9}, {%0,%1,%2,%3};"
        : "+f"(d[0]), "+f"(d[1]), "+f"(d[2]), "+f"(d[3])
        : "r"(a[0]), "r"(a[1]), "r"(a[2]), "r"(a[3]), "r"(b[0]), "r"(b[1]));
}
__device__ __forceinline__ void cpasync16(uint32_t dst, const void* src) {
    asm volatile("cp.async.cg.shared.global [%0], [%1], 16;"
                 :: "r"(dst), "l"(src) : "memory");
}
__device__ __forceinline__ float wexp(float f1v, float f2v, int a) {
    float e = f1v + f2v;
    e = fmaxf(e, 0.2f * e);               // leaky relu
    return (a > 0) ? __expf(e) : 0.f;
}

// ---------------------------------------------------------------------------
// Kernel A: h = input @ W   (known good)
// ---------------------------------------------------------------------------
__global__ __launch_bounds__(256) void k_gemm_h(const float* __restrict__ inp,
                                                const float* __restrict__ W) {
    __shared__ float inp_s[64][32];
    __shared__ float W_s[32][128];
    const int tid  = threadIdx.x;
    const int m0   = blockIdx.x * 64;
    const int fcol = (tid & 31) * 4;
    const int irow = (tid >> 5) * 8;

    float acc[8][4];
#pragma unroll
    for (int r = 0; r < 8; r++)
#pragma unroll
        for (int c = 0; c < 4; c++) acc[r][c] = 0.f;

    for (int kk = 0; kk < FIN; kk += 32) {
#pragma unroll
        for (int t = 0; t < 2; t++) {
            int idx = tid + t * 256;
            int r = idx >> 3, c = idx & 7;
            *(float4*)&inp_s[r][c * 4] =
                *(const float4*)&inp[(size_t)(m0 + r) * FIN + kk + c * 4];
        }
#pragma unroll
        for (int t = 0; t < 4; t++) {
            int idx = tid + t * 256;
            int k = idx >> 5, c = idx & 31;
            *(float4*)&W_s[k][c * 4] =
                *(const float4*)&W[(size_t)(kk + k) * FOUT + c * 4];
        }
        __syncthreads();
#pragma unroll
        for (int k = 0; k < 32; k++) {
            float4 bv = *(float4*)&W_s[k][fcol];
#pragma unroll
            for (int r = 0; r < 8; r++) {
                float a = inp_s[irow + r][k];
                acc[r][0] = fmaf(a, bv.x, acc[r][0]);
                acc[r][1] = fmaf(a, bv.y, acc[r][1]);
                acc[r][2] = fmaf(a, bv.z, acc[r][2]);
                acc[r][3] = fmaf(a, bv.w, acc[r][3]);
            }
        }
        __syncthreads();
    }
#pragma unroll
    for (int r = 0; r < 8; r++) {
        float4 o = make_float4(acc[r][0], acc[r][1], acc[r][2], acc[r][3]);
        *(float4*)&g_h[(size_t)(m0 + irow + r) * FOUT + fcol] = o;
    }
}

// ---------------------------------------------------------------------------
// Kernel B: f1/f2 projections
// ---------------------------------------------------------------------------
__global__ __launch_bounds__(256) void k_f12(const float* __restrict__ a1,
                                             const float* __restrict__ a2) {
    const int row  = blockIdx.x * 8 + (threadIdx.x >> 5);
    const int lane = threadIdx.x & 31;
    const float* hr = g_h + (size_t)row * FOUT;
    float s1 = 0.f, s2 = 0.f;
#pragma unroll
    for (int c = lane; c < FOUT; c += 32) {
        float hv = hr[c];
        s1 = fmaf(hv, __ldg(a1 + c), s1);
        s2 = fmaf(hv, __ldg(a2 + c), s2);
    }
#pragma unroll
    for (int o = 16; o; o >>= 1) {
        s1 += __shfl_xor_sync(0xffffffffu, s1, o);
        s2 += __shfl_xor_sync(0xffffffffu, s2, o);
    }
    if (lane == 0) { g_f1[row] = s1; g_f2[row] = s2; }
}

// ---------------------------------------------------------------------------
// Kernel C: transpose + bf16 hi/lo split
// ---------------------------------------------------------------------------
__global__ __launch_bounds__(256) void k_conv() {
    __shared__ float ts[32][33];
    const int b = blockIdx.z, f0 = blockIdx.y * 32, n0 = blockIdx.x * 32;
    const int tx = threadIdx.x, ty = threadIdx.y;
#pragma unroll
    for (int r = 0; r < 4; r++) {
        int n = n0 + ty + r * 8;
        ts[ty + r * 8][tx] = g_h[((size_t)(b * N_ + n)) * FOUT + f0 + tx];
    }
    __syncthreads();
#pragma unroll
    for (int r = 0; r < 4; r++) {
        int f = f0 + ty + r * 8;
        float v = ts[tx][ty + r * 8];
        __nv_bfloat16 hi = __float2bfloat16(v);
        float lo = v - __bfloat162float(hi);
        size_t o = ((size_t)(b * FOUT + f)) * N_ + n0 + tx;
        g_hT_hi[o] = hi;
        g_hT_lo[o] = __float2bfloat16(lo);
    }
}

// ---------------------------------------------------------------------------
// Kernel D: register-A HMMA attention.
// CTA = 128 i x 128 f; 8 warps = 4 m-groups (32 rows) x 2 n-groups (64 cols).
// A (P weights) generated DIRECTLY in mma fragment registers (no smem, no
// A-ldsm, no P barrier). H triple-buffered via cp.async, 1 sync/chunk.
// ---------------------------------------------------------------------------
#define SA_DEN   0
#define SA_H     512                  // buf (c%3)*32768; hi +0, lo +16384
#define SA_TOTAL (SA_H + 3 * 32768)   // 98,816 B

__global__ __launch_bounds__(256, 2) void k_attn_mma(const int* __restrict__ adj,
                                                     float* __restrict__ out) {
    extern __shared__ char smem[];
    const uint32_t sb = smem_u32(smem);
    const int tid = threadIdx.x;
    const int w = tid >> 5, lane = tid & 31;
    const int b = blockIdx.y, i0 = blockIdx.x * 128;
    const int gid = lane >> 2, qc = lane & 3;
    const int m0w = (w >> 1) * 32, n0w = (w & 1) * 64;

    // per-thread rows: m0w + ri*8 + gid, ri = 0..3
    float f1r[4];
#pragma unroll
    for (int ri = 0; ri < 4; ri++)
        f1r[ri] = g_f1[b * N_ + i0 + m0w + ri * 8 + gid];
    const float* f2b = g_f2 + b * N_;
    const int* abase = adj + (size_t)(b * N_ + i0 + m0w + gid) * N_;

    // B (H) ldmatrix addressing (swizzled 128B rows)
    const uint32_t xm = (uint32_t)((lane & 7) << 4);
    const uint32_t brow0 = (uint32_t)(n0w + ((lane & 16) >> 1) + (lane & 7)) * 128;
    uint32_t bcb[4];
#pragma unroll
    for (int k = 0; k < 4; k++)
        bcb[k] = (((uint32_t)(lane & 8) << 1) + 32u * k) ^ xm;

    float acc[2][8][4];
#pragma unroll
    for (int mt = 0; mt < 2; mt++)
#pragma unroll
        for (int nt = 0; nt < 8; nt++)
#pragma unroll
            for (int q = 0; q < 4; q++) acc[mt][nt][q] = 0.f;
    float den4[4] = {0.f, 0.f, 0.f, 0.f};

    // ---- H tile issue (hi 16KB + lo 16KB per chunk, swizzled) ----
    auto issueH = [&](int cj, int buf) {
        const int jj = cj * JC;
        const uint32_t hbn = sb + SA_H + (uint32_t)buf * 32768;
#pragma unroll
        for (int k = 0; k < 8; k++) {
            int idx = tid + k * 256;
            int bufl = idx >> 10;
            int rem = idx & 1023;
            int f = rem >> 3, jg = rem & 7;
            uint32_t dst = hbn + bufl * 16384 + (uint32_t)f * 128 +
                           (((uint32_t)jg * 16) ^ ((uint32_t)(f & 7) << 4));
            const __nv_bfloat16* src =
                (bufl ? g_hT_lo : g_hT_hi) + ((size_t)(b * FOUT + f)) * N_ + jj + jg * 8;
            cpasync16(dst, src);
        }
        asm volatile("cp.async.commit_group;" ::: "memory");
    };

    issueH(0, 0);
    issueH(1, 1);

    // adjacency prefetch for chunk0 ks0: pairs (jb, jb+8) for 4 rows
    int2 pre[8];
    {
        const int jb = 2 * qc;
#pragma unroll
        for (int ri = 0; ri < 4; ri++) {
            pre[2 * ri]     = *(const int2*)(abase + ri * 8 * N_ + jb);
            pre[2 * ri + 1] = *(const int2*)(abase + ri * 8 * N_ + jb + 8);
        }
    }

    for (int c = 0; c < NCH; c++) {
        const int j0 = c * JC;
        const uint32_t hb = sb + SA_H + (uint32_t)(c % 3) * 32768;

        // H(c) arrived; barrier also guarantees everyone finished chunk c-1,
        // so buffer (c+2)%3 (= H(c-1)'s) is free to refill.
        asm volatile("cp.async.wait_group 1;" ::: "memory");
        __syncthreads();
        {
            int cn = c + 2;
            if (cn > NCH - 1) cn = NCH - 1;   // dup-issue, never read
            issueH(cn, (c + 2) % 3);
        }

#pragma unroll
        for (int ks = 0; ks < 4; ks++) {
            const int jb = j0 + ks * 16 + 2 * qc;
            float2 f2a = *(const float2*)&f2b[jb];
            float2 f2c = *(const float2*)&f2b[jb + 8];

            // ---- generate A fragments (hi/lo) from prefetched adj ----
            uint32_t ah[2][4], al[2][4];
#pragma unroll
            for (int ri = 0; ri < 4; ri++) {
                const float f1v = f1r[ri];
                int2 ada = pre[2 * ri], adc = pre[2 * ri + 1];
                float w0 = wexp(f1v, f2a.x, ada.x);
                float w1 = wexp(f1v, f2a.y, ada.y);
                float w2 = wexp(f1v, f2c.x, adc.x);
                float w3 = wexp(f1v, f2c.y, adc.y);
                den4[ri] += (w0 + w1) + (w2 + w3);
                __nv_bfloat162 h01 = __floats2bfloat162_rn(w0, w1);
                __nv_bfloat162 h23 = __floats2bfloat162_rn(w2, w3);
                __nv_bfloat162 l01 = __floats2bfloat162_rn(
                    w0 - __bfloat162float(h01.x), w1 - __bfloat162float(h01.y));
                __nv_bfloat162 l23 = __floats2bfloat162_rn(
                    w2 - __bfloat162float(h23.x), w3 - __bfloat162float(h23.y));
                const int mt = ri >> 1, rr = ri & 1;
                ah[mt][rr]     = *(uint32_t*)&h01;
                ah[mt][rr + 2] = *(uint32_t*)&h23;
                al[mt][rr]     = *(uint32_t*)&l01;
                al[mt][rr + 2] = *(uint32_t*)&l23;
            }

            // ---- prefetch adj for next ks (lands during MMA) ----
            {
                int jn = (ks < 3) ? (jb + 16) : (j0 + JC + 2 * qc);
                if (jn >= N_) jn = 2 * qc;      // last chunk: dummy, unused
#pragma unroll
                for (int ri = 0; ri < 4; ri++) {
                    pre[2 * ri]     = *(const int2*)(abase + ri * 8 * N_ + jn);
                    pre[2 * ri + 1] = *(const int2*)(abase + ri * 8 * N_ + jn + 8);
                }
            }

            // ---- B hi: terms Phi*Hhi + Plo*Hhi ----
            uint32_t bh[16];
#pragma unroll
            for (int np = 0; np < 4; np++)
                ldsm_x4(bh + 4 * np, hb + brow0 + np * 2048 + bcb[ks]);
#pragma unroll
            for (int mt = 0; mt < 2; mt++)
#pragma unroll
                for (int nt = 0; nt < 8; nt++) {
                    mma16816(acc[mt][nt], ah[mt], bh + nt * 2);
                    mma16816(acc[mt][nt], al[mt], bh + nt * 2);
                }
            // ---- B lo: term Phi*Hlo ----
            uint32_t bl[16];
#pragma unroll
            for (int np = 0; np < 4; np++)
                ldsm_x4(bl + 4 * np, hb + 16384 + brow0 + np * 2048 + bcb[ks]);
#pragma unroll
            for (int mt = 0; mt < 2; mt++)
#pragma unroll
                for (int nt = 0; nt < 8; nt++)
                    mma16816(acc[mt][nt], ah[mt], bl + nt * 2);
        }
    }

    // ---- denominators: reduce over 4 lanes sharing a row ----
#pragma unroll
    for (int ri = 0; ri < 4; ri++) {
        den4[ri] += __shfl_xor_sync(0xffffffffu, den4[ri], 1);
        den4[ri] += __shfl_xor_sync(0xffffffffu, den4[ri], 2);
    }
    __syncthreads();   // all MMA reads of H done; reuse smem[0..512) for den
    if ((w & 1) == 0 && qc == 0) {
#pragma unroll
        for (int ri = 0; ri < 4; ri++)
            ((float*)smem)[m0w + ri * 8 + gid] = den4[ri];
    }
    __syncthreads();

    // ---- epilogue: divide, elu, store ----
    const float* dsm = (const float*)smem;
#pragma unroll
    for (int mt = 0; mt < 2; mt++) {
        int r0 = m0w + mt * 16 + gid;
        float d0 = dsm[r0], d1 = dsm[r0 + 8];
        float inv0 = (d0 > 0.f) ? (1.f / d0) : 0.f;
        float inv1 = (d1 > 0.f) ? (1.f / d1) : 0.f;
#pragma unroll
        for (int nt = 0; nt < 8; nt++) {
            int col = n0w + nt * 8 + 2 * qc;
            const float* a4 = acc[mt][nt];
            float v;
            float2 o;
            v = a4[0] * inv0; o.x = (v > 0.f) ? v : expm1f(v);
            v = a4[1] * inv0; o.y = (v > 0.f) ? v : expm1f(v);
            *(float2*)&out[((size_t)(b * N_ + i0 + r0)) * FOUT + col] = o;
            v = a4[2] * inv1; o.x = (v > 0.f) ? v : expm1f(v);
            v = a4[3] * inv1; o.y = (v > 0.f) ? v : expm1f(v);
            *(float2*)&out[((size_t)(b * N_ + i0 + r0 + 8)) * FOUT + col] = o;
        }
    }
}

// ---------------------------------------------------------------------------
extern "C" void kernel_launch(void* const* d_in, const int* in_sizes, int n_in,
                              void* d_out, int out_size) {
    const float* inp = (const float*)d_in[0];
    const int*   adj = (const int*)d_in[1];
    const float* W   = (const float*)d_in[2];
    const float* a1  = (const float*)d_in[3];
    const float* a2  = (const float*)d_in[4];
    float* out = (float*)d_out;

    cudaFuncSetAttribute(k_attn_mma, cudaFuncAttributeMaxDynamicSharedMemorySize,
                         SA_TOTAL);

    k_gemm_h<<<MTOT / 64, 256>>>(inp, W);
    dim3 gconv(N_ / 32, FOUT / 32, B_);
    k_conv<<<gconv, dim3(32, 8)>>>();
    k_f12<<<MTOT / 8, 256>>>(a1, a2);
    dim3 gattn(N_ / 128, B_);
    k_attn_mma<<<gattn, 256, SA_TOTAL>>>(adj, out);
}

// round 10
// speedup vs baseline: 1.3507x; 1.3507x over previous
#include <cuda_runtime.h>
#include <cuda_bf16.h>
#include <cstdint>
#include <cstddef>

#define B_    16
#define N_    2048
#define FIN   256
#define FOUT  128
#define MTOT  (B_ * N_)
#define JC    32
#define NCH   (N_ / JC)

// ---------------- device scratch (no allocation allowed) ----------------
__device__ float g_h[(size_t)MTOT * FOUT];                 // 16 MB
__device__ float g_f1[MTOT];
__device__ float g_f2[MTOT];
__device__ __nv_bfloat16 g_hT_hi[(size_t)B_ * FOUT * N_];  // 8 MB  [b][f][n]
__device__ __nv_bfloat16 g_hT_lo[(size_t)B_ * FOUT * N_];  // 8 MB

// ---------------- PTX helpers (sm_80-compatible only) ----------------
__device__ __forceinline__ uint32_t smem_u32(const void* p) {
    uint32_t a;
    asm("{ .reg .u64 t; cvta.to.shared.u64 t, %1; cvt.u32.u64 %0, t; }"
        : "=r"(a) : "l"(p));
    return a;
}
__device__ __forceinline__ void ldsm_x4(uint32_t* r, uint32_t a) {
    asm volatile("ldmatrix.sync.aligned.m8n8.x4.shared.b16 {%0,%1,%2,%3}, [%4];"
                 : "=r"(r[0]), "=r"(r[1]), "=r"(r[2]), "=r"(r[3]) : "r"(a));
}
__device__ __forceinline__ void mma16816(float* d, const uint32_t* a,
                                         const uint32_t* b) {
    asm volatile(
        "mma.sync.aligned.m16n8k16.row.col.f32.bf16.bf16.f32 "
        "{%0,%1,%2,%3}, {%4,%5,%6,%7}, {%8,%9}, {%0,%1,%2,%3};"
        : "+f"(d[0]), "+f"(d[1]), "+f"(d[2]), "+f"(d[3])
        : "r"(a[0]), "r"(a[1]), "r"(a[2]), "r"(a[3]), "r"(b[0]), "r"(b[1]));
}
__device__ __forceinline__ void cpasync16(uint32_t dst, const void* src) {
    asm volatile("cp.async.cg.shared.global [%0], [%1], 16;"
                 :: "r"(dst), "l"(src) : "memory");
}

// ---------------------------------------------------------------------------
// Kernel A: h = input @ W   (known good)
// ---------------------------------------------------------------------------
__global__ __launch_bounds__(256) void k_gemm_h(const float* __restrict__ inp,
                                                const float* __restrict__ W) {
    __shared__ float inp_s[64][32];
    __shared__ float W_s[32][128];
    const int tid  = threadIdx.x;
    const int m0   = blockIdx.x * 64;
    const int fcol = (tid & 31) * 4;
    const int irow = (tid >> 5) * 8;

    float acc[8][4];
#pragma unroll
    for (int r = 0; r < 8; r++)
#pragma unroll
        for (int c = 0; c < 4; c++) acc[r][c] = 0.f;

    for (int kk = 0; kk < FIN; kk += 32) {
#pragma unroll
        for (int t = 0; t < 2; t++) {
            int idx = tid + t * 256;
            int r = idx >> 3, c = idx & 7;
            *(float4*)&inp_s[r][c * 4] =
                *(const float4*)&inp[(size_t)(m0 + r) * FIN + kk + c * 4];
        }
#pragma unroll
        for (int t = 0; t < 4; t++) {
            int idx = tid + t * 256;
            int k = idx >> 5, c = idx & 31;
            *(float4*)&W_s[k][c * 4] =
                *(const float4*)&W[(size_t)(kk + k) * FOUT + c * 4];
        }
        __syncthreads();
#pragma unroll
        for (int k = 0; k < 32; k++) {
            float4 bv = *(float4*)&W_s[k][fcol];
#pragma unroll
            for (int r = 0; r < 8; r++) {
                float a = inp_s[irow + r][k];
                acc[r][0] = fmaf(a, bv.x, acc[r][0]);
                acc[r][1] = fmaf(a, bv.y, acc[r][1]);
                acc[r][2] = fmaf(a, bv.z, acc[r][2]);
                acc[r][3] = fmaf(a, bv.w, acc[r][3]);
            }
        }
        __syncthreads();
    }
#pragma unroll
    for (int r = 0; r < 8; r++) {
        float4 o = make_float4(acc[r][0], acc[r][1], acc[r][2], acc[r][3]);
        *(float4*)&g_h[(size_t)(m0 + irow + r) * FOUT + fcol] = o;
    }
}

// ---------------------------------------------------------------------------
// Kernel B: f1/f2 projections
// ---------------------------------------------------------------------------
__global__ __launch_bounds__(256) void k_f12(const float* __restrict__ a1,
                                             const float* __restrict__ a2) {
    const int row  = blockIdx.x * 8 + (threadIdx.x >> 5);
    const int lane = threadIdx.x & 31;
    const float* hr = g_h + (size_t)row * FOUT;
    float s1 = 0.f, s2 = 0.f;
#pragma unroll
    for (int c = lane; c < FOUT; c += 32) {
        float hv = hr[c];
        s1 = fmaf(hv, __ldg(a1 + c), s1);
        s2 = fmaf(hv, __ldg(a2 + c), s2);
    }
#pragma unroll
    for (int o = 16; o; o >>= 1) {
        s1 += __shfl_xor_sync(0xffffffffu, s1, o);
        s2 += __shfl_xor_sync(0xffffffffu, s2, o);
    }
    if (lane == 0) { g_f1[row] = s1; g_f2[row] = s2; }
}

// ---------------------------------------------------------------------------
// Kernel C: transpose + bf16 hi/lo split
// ---------------------------------------------------------------------------
__global__ __launch_bounds__(256) void k_conv() {
    __shared__ float ts[32][33];
    const int b = blockIdx.z, f0 = blockIdx.y * 32, n0 = blockIdx.x * 32;
    const int tx = threadIdx.x, ty = threadIdx.y;
#pragma unroll
    for (int r = 0; r < 4; r++) {
        int n = n0 + ty + r * 8;
        ts[ty + r * 8][tx] = g_h[((size_t)(b * N_ + n)) * FOUT + f0 + tx];
    }
    __syncthreads();
#pragma unroll
    for (int r = 0; r < 4; r++) {
        int f = f0 + ty + r * 8;
        float v = ts[tx][ty + r * 8];
        __nv_bfloat16 hi = __float2bfloat16(v);
        float lo = v - __bfloat162float(hi);
        size_t o = ((size_t)(b * FOUT + f)) * N_ + n0 + tx;
        g_hT_hi[o] = hi;
        g_hT_lo[o] = __float2bfloat16(lo);
    }
}

// ---------------------------------------------------------------------------
// Kernel D: chunk-pipelined HMMA attention (R8 structure, B-load FIXED).
// CTA = 128 i x 128 f; warps: 2 m-groups (64) x 4 n-groups (32). JC=32.
// P and H double-buffered INSIDE the 128B swizzled rows (64B half per chunk
// parity). One barrier per chunk; P-gen(c+1) runs after MMA(c) issue so
// scalar work overlaps tensor drain. adj prefetched 2 chunks ahead.
// ---------------------------------------------------------------------------
#define SA_DEN   0
#define SA_P     512                    // Phi +0, Plo +16384 (both buffers in-row)
#define SA_H     (SA_P + 32768)         // Hhi +0, Hlo +16384 (both buffers in-row)
#define SA_TOTAL (SA_H + 32768)         // 66,048 B

__global__ __launch_bounds__(256, 2) void k_attn_mma(const int* __restrict__ adj,
                                                     float* __restrict__ out) {
    extern __shared__ char smem[];
    const uint32_t sb = smem_u32(smem);
    const int tid = threadIdx.x;
    const int w = tid >> 5, lane = tid & 31;
    const int b = blockIdx.y, i0 = blockIdx.x * 128;

    // ---- P-gen mapping: 2 threads per i-row, 16 j each ----
    const int pi = tid >> 1;
    const int pj = (tid & 1) * 16;
    const float f1v = g_f1[b * N_ + i0 + pi];
    const float* f2b = g_f2 + b * N_;
    const int* adjr = adj + (size_t)(b * N_ + i0 + pi) * N_;
    const uint32_t prow = (uint32_t)pi * 128;
    const uint32_t pxm = (uint32_t)((pi & 7) << 4);
    float den = 0.f;

    // ---- MMA mapping: warp -> 64x32 tile; swizzled ldmatrix bases ----
    const int m0 = (w >> 2) * 64, n0 = (w & 3) * 32;
    const uint32_t xm = (uint32_t)((lane & 7) << 4);
    const uint32_t arow = sb + SA_P + (uint32_t)(m0 + (lane & 15)) * 128;
    const uint32_t brow0 = sb + SA_H +
        (uint32_t)(n0 + ((lane & 16) >> 1) + (lane & 7)) * 128;
    const uint32_t acb0 = (uint32_t)(lane & 16);
    const uint32_t bcb0 = (uint32_t)((lane & 8) << 1);

    float acc[16][4];
#pragma unroll
    for (int t = 0; t < 16; t++)
#pragma unroll
        for (int q = 0; q < 4; q++) acc[t][q] = 0.f;

    // ---- H chunk issue (hi+lo, 16 KB, 4 cp.async per thread) ----
    auto issueH = [&](int cj) {
        const int jj = cj * JC;
        const uint32_t pb64 = (uint32_t)(cj & 1) * 64;
#pragma unroll
        for (int k = 0; k < 4; k++) {
            int idx = tid + k * 256;
            int bufl = idx >> 9;
            int rem = idx & 511;
            int f = rem >> 2, jg = rem & 3;
            uint32_t dst = sb + SA_H + bufl * 16384 + (uint32_t)f * 128 +
                           ((pb64 + (uint32_t)jg * 16) ^ ((uint32_t)(f & 7) << 4));
            const __nv_bfloat16* src =
                (bufl ? g_hT_lo : g_hT_hi) + ((size_t)(b * FOUT + f)) * N_ + jj + jg * 8;
            cpasync16(dst, src);
        }
        asm volatile("cp.async.commit_group;" ::: "memory");
    };

    // ---- P-gen for chunk cj from prefetched adjacency ----
    auto genP = [&](int cj, const int4* av) {
        const int jj = cj * JC + pj;
        const uint32_t pb64 = (uint32_t)(cj & 1) * 64;
#pragma unroll
        for (int q = 0; q < 4; q++) {
            float4 f2v = *(const float4*)&f2b[jj + q * 4];
            float e0 = f1v + f2v.x, e1 = f1v + f2v.y;
            float e2 = f1v + f2v.z, e3 = f1v + f2v.w;
            e0 = fmaxf(e0, 0.2f * e0);
            e1 = fmaxf(e1, 0.2f * e1);
            e2 = fmaxf(e2, 0.2f * e2);
            e3 = fmaxf(e3, 0.2f * e3);
            float w0 = (av[q].x > 0) ? __expf(e0) : 0.f;
            float w1 = (av[q].y > 0) ? __expf(e1) : 0.f;
            float w2 = (av[q].z > 0) ? __expf(e2) : 0.f;
            float w3 = (av[q].w > 0) ? __expf(e3) : 0.f;
            den += (w0 + w1) + (w2 + w3);
            __nv_bfloat162 h01 = __floats2bfloat162_rn(w0, w1);
            __nv_bfloat162 h23 = __floats2bfloat162_rn(w2, w3);
            __nv_bfloat162 l01 = __floats2bfloat162_rn(
                w0 - __bfloat162float(h01.x), w1 - __bfloat162float(h01.y));
            __nv_bfloat162 l23 = __floats2bfloat162_rn(
                w2 - __bfloat162float(h23.x), w3 - __bfloat162float(h23.y));
            uint32_t off = prow + ((pb64 + (uint32_t)(pj + q * 4) * 2) ^ pxm);
            unsigned long long vhi = (unsigned long long)*(uint32_t*)&h01 |
                                     ((unsigned long long)*(uint32_t*)&h23 << 32);
            unsigned long long vlo = (unsigned long long)*(uint32_t*)&l01 |
                                     ((unsigned long long)*(uint32_t*)&l23 << 32);
            *(unsigned long long*)(smem + SA_P + off) = vhi;
            *(unsigned long long*)(smem + SA_P + 16384 + off) = vlo;
        }
    };

    // ---- prologue: adj(0) -> P(0); prefetch adj(1); issue H(0) ----
    int4 apre[4];
#pragma unroll
    for (int q = 0; q < 4; q++)
        apre[q] = *(const int4*)(adjr + pj + q * 4);
    issueH(0);
    genP(0, apre);
#pragma unroll
    for (int q = 0; q < 4; q++)
        apre[q] = *(const int4*)(adjr + JC + pj + q * 4);

    for (int c = 0; c < NCH; c++) {
        const uint32_t pb64 = (uint32_t)(c & 1) * 64;

        // H(c) arrived (own copies); barrier gives cross-thread visibility of
        // P(c)/H(c) and frees P[(c+1)&1]/H[(c+1)&1] (last read by MMA(c-1)).
        asm volatile("cp.async.wait_group 0;" ::: "memory");
        __syncthreads();

        if (c + 1 < NCH) issueH(c + 1);

        // ---- MMA(c): issue tensor work first ----
#pragma unroll
        for (int ks = 0; ks < 2; ks++) {
            const uint32_t cb = pb64 + (uint32_t)ks * 32;
            const uint32_t bco = (cb + bcb0) ^ xm;
            const uint32_t aco = (cb + acb0) ^ xm;
            uint32_t bh[8], bl[8];
            ldsm_x4(bh,     brow0 + bco);            // cols n0..n0+15
            ldsm_x4(bh + 4, brow0 + 2048 + bco);     // cols n0+16..n0+31
            ldsm_x4(bl,     brow0 + 16384 + bco);
            ldsm_x4(bl + 4, brow0 + 16384 + 2048 + bco);
            uint32_t ah[2][4], al[2][4];
#pragma unroll
            for (int mt = 0; mt < 4; mt++) {
                uint32_t* ahp = ah[mt & 1];
                uint32_t* alp = al[mt & 1];
                ldsm_x4(ahp, arow + mt * 2048 + aco);
                ldsm_x4(alp, arow + 16384 + mt * 2048 + aco);
#pragma unroll
                for (int nt = 0; nt < 4; nt++) {
                    mma16816(acc[mt * 4 + nt], ahp, bh + nt * 2);
                    mma16816(acc[mt * 4 + nt], alp, bh + nt * 2);
                    mma16816(acc[mt * 4 + nt], ahp, bl + nt * 2);
                }
            }
        }

        // ---- P-gen(c+1) overlaps tensor drain; adj(c+2) prefetch ----
        if (c + 1 < NCH) {
            genP(c + 1, apre);
            int cn = (c + 2 < NCH) ? (c + 2) : (NCH - 1);
#pragma unroll
            for (int q = 0; q < 4; q++)
                apre[q] = *(const int4*)(adjr + cn * JC + pj + q * 4);
        }
    }

    // ---- denominator: pair-reduce ----
    den += __shfl_xor_sync(0xffffffffu, den, 1);
    __syncthreads();
    if ((tid & 1) == 0) ((float*)(smem + SA_DEN))[pi] = den;
    __syncthreads();

    // ---- epilogue: divide, elu, store ----
    const float* dsm = (const float*)(smem + SA_DEN);
    const int gid = lane >> 2, qc = lane & 3;
#pragma unroll
    for (int mt = 0; mt < 4; mt++) {
        int r0 = m0 + mt * 16 + gid;
        float d0 = dsm[r0], d1 = dsm[r0 + 8];
        float inv0 = (d0 > 0.f) ? (1.f / d0) : 0.f;
        float inv1 = (d1 > 0.f) ? (1.f / d1) : 0.f;
#pragma unroll
        for (int nt = 0; nt < 4; nt++) {
            int col = n0 + nt * 8 + 2 * qc;
            const float* a4 = acc[mt * 4 + nt];
            float v;
            float2 o;
            v = a4[0] * inv0; o.x = (v > 0.f) ? v : expm1f(v);
            v = a4[1] * inv0; o.y = (v > 0.f) ? v : expm1f(v);
            *(float2*)&out[((size_t)(b * N_ + i0 + r0)) * FOUT + col] = o;
            v = a4[2] * inv1; o.x = (v > 0.f) ? v : expm1f(v);
            v = a4[3] * inv1; o.y = (v > 0.f) ? v : expm1f(v);
            *(float2*)&out[((size_t)(b * N_ + i0 + r0 + 8)) * FOUT + col] = o;
        }
    }
}

// ---------------------------------------------------------------------------
extern "C" void kernel_launch(void* const* d_in, const int* in_sizes, int n_in,
                              void* d_out, int out_size) {
    const float* inp = (const float*)d_in[0];
    const int*   adj = (const int*)d_in[1];
    const float* W   = (const float*)d_in[2];
    const float* a1  = (const float*)d_in[3];
    const float* a2  = (const float*)d_in[4];
    float* out = (float*)d_out;

    cudaFuncSetAttribute(k_attn_mma, cudaFuncAttributeMaxDynamicSharedMemorySize,
                         SA_TOTAL);

    k_gemm_h<<<MTOT / 64, 256>>>(inp, W);
    dim3 gconv(N_ / 32, FOUT / 32, B_);
    k_conv<<<gconv, dim3(32, 8)>>>();
    k_f12<<<MTOT / 8, 256>>>(a1, a2);
    dim3 gattn(N_ / 128, B_);
    k_attn_mma<<<gattn, 256, SA_TOTAL>>>(adj, out);
}

// round 12
// speedup vs baseline: 1.6022x; 1.1862x over previous
#include <cuda_runtime.h>
#include <cuda_bf16.h>
#include <cuda_fp16.h>
#include <cstdint>
#include <cstddef>

#define B_    16
#define N_    2048
#define FIN   256
#define FOUT  128
#define MTOT  (B_ * N_)
#define JC    32
#define NCH   (N_ / JC)

// ---------------- device scratch (no allocation allowed) ----------------
__device__ float g_h[(size_t)MTOT * FOUT];              // 16 MB
__device__ float g_f1[MTOT];
__device__ float g_f2[MTOT];
__device__ float g_f2max[B_];
__device__ __half g_hT_hi[(size_t)B_ * FOUT * N_];      // 8 MB  [b][f][n]
__device__ __half g_hT_lo[(size_t)B_ * FOUT * N_];      // 8 MB

// ---------------- PTX helpers (sm_80-compatible only) ----------------
__device__ __forceinline__ uint32_t smem_u32(const void* p) {
    uint32_t a;
    asm("{ .reg .u64 t; cvta.to.shared.u64 t, %1; cvt.u32.u64 %0, t; }"
        : "=r"(a) : "l"(p));
    return a;
}
__device__ __forceinline__ void ldsm_x4(uint32_t* r, uint32_t a) {
    asm volatile("ldmatrix.sync.aligned.m8n8.x4.shared.b16 {%0,%1,%2,%3}, [%4];"
                 : "=r"(r[0]), "=r"(r[1]), "=r"(r[2]), "=r"(r[3]) : "r"(a));
}
__device__ __forceinline__ void mma16816h(float* d, const uint32_t* a,
                                          const uint32_t* b) {
    asm volatile(
        "mma.sync.aligned.m16n8k16.row.col.f32.f16.f16.f32 "
        "{%0,%1,%2,%3}, {%4,%5,%6,%7}, {%8,%9}, {%0,%1,%2,%3};"
        : "+f"(d[0]), "+f"(d[1]), "+f"(d[2]), "+f"(d[3])
        : "r"(a[0]), "r"(a[1]), "r"(a[2]), "r"(a[3]), "r"(b[0]), "r"(b[1]));
}
__device__ __forceinline__ void cpasync16(uint32_t dst, const void* src) {
    asm volatile("cp.async.cg.shared.global [%0], [%1], 16;"
                 :: "r"(dst), "l"(src) : "memory");
}

// ---------------------------------------------------------------------------
// Kernel A: h = input @ W   (known good)
// ---------------------------------------------------------------------------
__global__ __launch_bounds__(256) void k_gemm_h(const float* __restrict__ inp,
                                                const float* __restrict__ W) {
    __shared__ float inp_s[64][32];
    __shared__ float W_s[32][128];
    const int tid  = threadIdx.x;
    const int m0   = blockIdx.x * 64;
    const int fcol = (tid & 31) * 4;
    const int irow = (tid >> 5) * 8;

    float acc[8][4];
#pragma unroll
    for (int r = 0; r < 8; r++)
#pragma unroll
        for (int c = 0; c < 4; c++) acc[r][c] = 0.f;

    for (int kk = 0; kk < FIN; kk += 32) {
#pragma unroll
        for (int t = 0; t < 2; t++) {
            int idx = tid + t * 256;
            int r = idx >> 3, c = idx & 7;
            *(float4*)&inp_s[r][c * 4] =
                *(const float4*)&inp[(size_t)(m0 + r) * FIN + kk + c * 4];
        }
#pragma unroll
        for (int t = 0; t < 4; t++) {
            int idx = tid + t * 256;
            int k = idx >> 5, c = idx & 31;
            *(float4*)&W_s[k][c * 4] =
                *(const float4*)&W[(size_t)(kk + k) * FOUT + c * 4];
        }
        __syncthreads();
#pragma unroll
        for (int k = 0; k < 32; k++) {
            float4 bv = *(float4*)&W_s[k][fcol];
#pragma unroll
            for (int r = 0; r < 8; r++) {
                float a = inp_s[irow + r][k];
                acc[r][0] = fmaf(a, bv.x, acc[r][0]);
                acc[r][1] = fmaf(a, bv.y, acc[r][1]);
                acc[r][2] = fmaf(a, bv.z, acc[r][2]);
                acc[r][3] = fmaf(a, bv.w, acc[r][3]);
            }
        }
        __syncthreads();
    }
#pragma unroll
    for (int r = 0; r < 8; r++) {
        float4 o = make_float4(acc[r][0], acc[r][1], acc[r][2], acc[r][3]);
        *(float4*)&g_h[(size_t)(m0 + irow + r) * FOUT + fcol] = o;
    }
}

// ---------------------------------------------------------------------------
// Kernel B: f1/f2 projections
// ---------------------------------------------------------------------------
__global__ __launch_bounds__(256) void k_f12(const float* __restrict__ a1,
                                             const float* __restrict__ a2) {
    const int row  = blockIdx.x * 8 + (threadIdx.x >> 5);
    const int lane = threadIdx.x & 31;
    const float* hr = g_h + (size_t)row * FOUT;
    float s1 = 0.f, s2 = 0.f;
#pragma unroll
    for (int c = lane; c < FOUT; c += 32) {
        float hv = hr[c];
        s1 = fmaf(hv, __ldg(a1 + c), s1);
        s2 = fmaf(hv, __ldg(a2 + c), s2);
    }
#pragma unroll
    for (int o = 16; o; o >>= 1) {
        s1 += __shfl_xor_sync(0xffffffffu, s1, o);
        s2 += __shfl_xor_sync(0xffffffffu, s2, o);
    }
    if (lane == 0) { g_f1[row] = s1; g_f2[row] = s2; }
}

// ---------------------------------------------------------------------------
// Kernel B2: per-batch max of f2 (for the softmax shift bound)
// ---------------------------------------------------------------------------
__global__ __launch_bounds__(256) void k_f2max() {
    const int b = blockIdx.x, tid = threadIdx.x;
    float m = -1e30f;
    for (int i = tid; i < N_; i += 256) m = fmaxf(m, g_f2[b * N_ + i]);
#pragma unroll
    for (int o = 16; o; o >>= 1) m = fmaxf(m, __shfl_xor_sync(0xffffffffu, m, o));
    __shared__ float s[8];
    if ((tid & 31) == 0) s[tid >> 5] = m;
    __syncthreads();
    if (tid < 8) {
        float mm = s[tid];
#pragma unroll
        for (int o = 4; o; o >>= 1) mm = fmaxf(mm, __shfl_xor_sync(0xffu, mm, o));
        if (tid == 0) g_f2max[b] = mm;
    }
}

// ---------------------------------------------------------------------------
// Kernel C: transpose + fp16 hi/lo split: g_hT_*[b][f][n] from g_h[b][n][f]
// ---------------------------------------------------------------------------
__global__ __launch_bounds__(256) void k_conv() {
    __shared__ float ts[32][33];
    const int b = blockIdx.z, f0 = blockIdx.y * 32, n0 = blockIdx.x * 32;
    const int tx = threadIdx.x, ty = threadIdx.y;
#pragma unroll
    for (int r = 0; r < 4; r++) {
        int n = n0 + ty + r * 8;
        ts[ty + r * 8][tx] = g_h[((size_t)(b * N_ + n)) * FOUT + f0 + tx];
    }
    __syncthreads();
#pragma unroll
    for (int r = 0; r < 4; r++) {
        int f = f0 + ty + r * 8;
        float v = ts[tx][ty + r * 8];
        __half hi = __float2half_rn(v);
        float lo = v - __half2float(hi);
        size_t o = ((size_t)(b * FOUT + f)) * N_ + n0 + tx;
        g_hT_hi[o] = hi;
        g_hT_lo[o] = __float2half_rn(lo);
    }
}

// ---------------------------------------------------------------------------
// Kernel D: chunk-pipelined HMMA attention, fp16 2-term max-shifted.
// w = exp(leaky(f1+f2) - M_i) in (0,1] -> single fp16 P; H fp16 hi/lo.
// acc += P*Hhi + P*Hlo. Same R10 pipeline: one barrier/chunk, P-gen(c+1)
// after MMA(c) issue, adj prefetched 2 chunks ahead, in-row double buffers.
// ---------------------------------------------------------------------------
#define SA_DEN   0
#define SA_P     512                    // fp16 P, both chunk buffers in-row
#define SA_H     (SA_P + 16384)         // Hhi +0, Hlo +16384
#define SA_TOTAL (SA_H + 32768)         // 49,664 B

__global__ __launch_bounds__(256, 2) void k_attn_mma(const int* __restrict__ adj,
                                                     float* __restrict__ out) {
    extern __shared__ char smem[];
    const uint32_t sb = smem_u32(smem);
    const int tid = threadIdx.x;
    const int w = tid >> 5, lane = tid & 31;
    const int b = blockIdx.y, i0 = blockIdx.x * 128;

    // ---- P-gen mapping: 2 threads per i-row, 16 j each ----
    const int pi = tid >> 1;
    const int pj = (tid & 1) * 16;
    const float f1v = g_f1[b * N_ + i0 + pi];
    const float mf2 = g_f2max[b];
    const float tM  = f1v + mf2;
    const float Mi  = fmaxf(tM, 0.2f * tM);   // leaky(f1 + max f2) >= any masked e
    const float* f2b = g_f2 + b * N_;
    const int* adjr = adj + (size_t)(b * N_ + i0 + pi) * N_;
    const uint32_t prow = (uint32_t)pi * 128;
    const uint32_t pxm = (uint32_t)((pi & 7) << 4);
    float den = 0.f;

    // ---- MMA mapping: warp -> 64x32 tile; swizzled ldmatrix bases ----
    const int m0 = (w >> 2) * 64, n0 = (w & 3) * 32;
    const uint32_t xm = (uint32_t)((lane & 7) << 4);
    const uint32_t arow = sb + SA_P + (uint32_t)(m0 + (lane & 15)) * 128;
    const uint32_t brow0 = sb + SA_H +
        (uint32_t)(n0 + ((lane & 16) >> 1) + (lane & 7)) * 128;
    const uint32_t acb0 = (uint32_t)(lane & 16);
    const uint32_t bcb0 = (uint32_t)((lane & 8) << 1);

    float acc[16][4];
#pragma unroll
    for (int t = 0; t < 16; t++)
#pragma unroll
        for (int q = 0; q < 4; q++) acc[t][q] = 0.f;

    // ---- H chunk issue (hi+lo, 16 KB, 4 cp.async per thread) ----
    auto issueH = [&](int cj) {
        const int jj = cj * JC;
        const uint32_t pb64 = (uint32_t)(cj & 1) * 64;
#pragma unroll
        for (int k = 0; k < 4; k++) {
            int idx = tid + k * 256;
            int bufl = idx >> 9;
            int rem = idx & 511;
            int f = rem >> 2, jg = rem & 3;
            uint32_t dst = sb + SA_H + bufl * 16384 + (uint32_t)f * 128 +
                           ((pb64 + (uint32_t)jg * 16) ^ ((uint32_t)(f & 7) << 4));
            const __half* src =
                (bufl ? g_hT_lo : g_hT_hi) + ((size_t)(b * FOUT + f)) * N_ + jj + jg * 8;
            cpasync16(dst, src);
        }
        asm volatile("cp.async.commit_group;" ::: "memory");
    };

    // ---- P-gen for chunk cj from prefetched adjacency ----
    auto genP = [&](int cj, const int4* av) {
        const int jj = cj * JC + pj;
        const uint32_t pb64 = (uint32_t)(cj & 1) * 64;
#pragma unroll
        for (int q = 0; q < 4; q++) {
            float4 f2v = *(const float4*)&f2b[jj + q * 4];
            float e0 = f1v + f2v.x, e1 = f1v + f2v.y;
            float e2 = f1v + f2v.z, e3 = f1v + f2v.w;
            e0 = fmaxf(e0, 0.2f * e0) - Mi;
            e1 = fmaxf(e1, 0.2f * e1) - Mi;
            e2 = fmaxf(e2, 0.2f * e2) - Mi;
            e3 = fmaxf(e3, 0.2f * e3) - Mi;
            float w0 = (av[q].x > 0) ? __expf(e0) : 0.f;
            float w1 = (av[q].y > 0) ? __expf(e1) : 0.f;
            float w2 = (av[q].z > 0) ? __expf(e2) : 0.f;
            float w3 = (av[q].w > 0) ? __expf(e3) : 0.f;
            den += (w0 + w1) + (w2 + w3);
            __half2 p01 = __floats2half2_rn(w0, w1);
            __half2 p23 = __floats2half2_rn(w2, w3);
            uint32_t off = prow + ((pb64 + (uint32_t)(pj + q * 4) * 2) ^ pxm);
            unsigned long long vhi = (unsigned long long)*(uint32_t*)&p01 |
                                     ((unsigned long long)*(uint32_t*)&p23 << 32);
            *(unsigned long long*)(smem + SA_P + off) = vhi;
        }
    };

    // ---- prologue: adj(0) -> P(0); prefetch adj(1); issue H(0) ----
    int4 apre[4];
#pragma unroll
    for (int q = 0; q < 4; q++)
        apre[q] = *(const int4*)(adjr + pj + q * 4);
    issueH(0);
    genP(0, apre);
#pragma unroll
    for (int q = 0; q < 4; q++)
        apre[q] = *(const int4*)(adjr + JC + pj + q * 4);

    for (int c = 0; c < NCH; c++) {
        const uint32_t pb64 = (uint32_t)(c & 1) * 64;

        // H(c) arrived (own copies); barrier gives cross-thread visibility of
        // P(c)/H(c) and frees P[(c+1)&1]/H[(c+1)&1] (last read by MMA(c-1)).
        asm volatile("cp.async.wait_group 0;" ::: "memory");
        __syncthreads();

        if (c + 1 < NCH) issueH(c + 1);

        // ---- MMA(c): 2 terms, issue tensor work first ----
#pragma unroll
        for (int ks = 0; ks < 2; ks++) {
            const uint32_t cb = pb64 + (uint32_t)ks * 32;
            const uint32_t bco = (cb + bcb0) ^ xm;
            const uint32_t aco = (cb + acb0) ^ xm;
            uint32_t bh[8], bl[8];
            ldsm_x4(bh,     brow0 + bco);            // Hhi cols n0..n0+15
            ldsm_x4(bh + 4, brow0 + 2048 + bco);     // Hhi cols n0+16..n0+31
            ldsm_x4(bl,     brow0 + 16384 + bco);    // Hlo
            ldsm_x4(bl + 4, brow0 + 16384 + 2048 + bco);
            uint32_t ah[2][4];
#pragma unroll
            for (int mt = 0; mt < 4; mt++) {
                uint32_t* ahp = ah[mt & 1];
                ldsm_x4(ahp, arow + mt * 2048 + aco);
#pragma unroll
                for (int nt = 0; nt < 4; nt++) {
                    mma16816h(acc[mt * 4 + nt], ahp, bh + nt * 2);
                    mma16816h(acc[mt * 4 + nt], ahp, bl + nt * 2);
                }
            }
        }

        // ---- P-gen(c+1) overlaps tensor drain; adj(c+2) prefetch ----
        if (c + 1 < NCH) {
            genP(c + 1, apre);
            int cn = (c + 2 < NCH) ? (c + 2) : (NCH - 1);
#pragma unroll
            for (int q = 0; q < 4; q++)
                apre[q] = *(const int4*)(adjr + cn * JC + pj + q * 4);
        }
    }

    // ---- denominator: pair-reduce ----
    den += __shfl_xor_sync(0xffffffffu, den, 1);
    __syncthreads();
    if ((tid & 1) == 0) ((float*)(smem + SA_DEN))[pi] = den;
    __syncthreads();

    // ---- epilogue: divide, elu, store ----
    const float* dsm = (const float*)(smem + SA_DEN);
    const int gid = lane >> 2, qc = lane & 3;
#pragma unroll
    for (int mt = 0; mt < 4; mt++) {
        int r0 = m0 + mt * 16 + gid;
        float d0 = dsm[r0], d1 = dsm[r0 + 8];
        float inv0 = (d0 > 0.f) ? (1.f / d0) : 0.f;
        float inv1 = (d1 > 0.f) ? (1.f / d1) : 0.f;
#pragma unroll
        for (int nt = 0; nt < 4; nt++) {
            int col = n0 + nt * 8 + 2 * qc;
            const float* a4 = acc[mt * 4 + nt];
            float v;
            float2 o;
            v = a4[0] * inv0; o.x = (v > 0.f) ? v : expm1f(v);
            v = a4[1] * inv0; o.y = (v > 0.f) ? v : expm1f(v);
            *(float2*)&out[((size_t)(b * N_ + i0 + r0)) * FOUT + col] = o;
            v = a4[2] * inv1; o.x = (v > 0.f) ? v : expm1f(v);
            v = a4[3] * inv1; o.y = (v > 0.f) ? v : expm1f(v);
            *(float2*)&out[((size_t)(b * N_ + i0 + r0 + 8)) * FOUT + col] = o;
        }
    }
}

// ---------------------------------------------------------------------------
extern "C" void kernel_launch(void* const* d_in, const int* in_sizes, int n_in,
                              void* d_out, int out_size) {
    const float* inp = (const float*)d_in[0];
    const int*   adj = (const int*)d_in[1];
    const float* W   = (const float*)d_in[2];
    const float* a1  = (const float*)d_in[3];
    const float* a2  = (const float*)d_in[4];
    float* out = (float*)d_out;

    cudaFuncSetAttribute(k_attn_mma, cudaFuncAttributeMaxDynamicSharedMemorySize,
                         SA_TOTAL);

    k_gemm_h<<<MTOT / 64, 256>>>(inp, W);
    dim3 gconv(N_ / 32, FOUT / 32, B_);
    k_conv<<<gconv, dim3(32, 8)>>>();
    k_f12<<<MTOT / 8, 256>>>(a1, a2);
    k_f2max<<<B_, 256>>>();
    dim3 gattn(N_ / 128, B_);
    k_attn_mma<<<gattn, 256, SA_TOTAL>>>(adj, out);
}

// round 16
// speedup vs baseline: 1.8422x; 1.1498x over previous
#include <cuda_runtime.h>
#include <cuda_bf16.h>
#include <cuda_fp16.h>
#include <cstdint>
#include <cstddef>

#define B_    16
#define N_    2048
#define FIN   256
#define FOUT  128
#define MTOT  (B_ * N_)
#define JC    32
#define NCH   (N_ / JC)
#define NCHG  (FIN / 32)

// ---------------- device scratch (no allocation allowed) ----------------
__device__ float g_f1[MTOT];
__device__ float g_f2[MTOT];
__device__ float g_f2max[B_];
__device__ __half g_i_hi[(size_t)MTOT * FIN];           // 16 MB [m][k]
__device__ __half g_i_lo[(size_t)MTOT * FIN];           // 16 MB
__device__ __half g_wT_hi[(size_t)FOUT * FIN];          // 64 KB [f][k]
__device__ __half g_wT_lo[(size_t)FOUT * FIN];
__device__ __half g_hT_hi[(size_t)B_ * FOUT * N_];      // 8 MB  [b][f][n]
__device__ __half g_hT_lo[(size_t)B_ * FOUT * N_];      // 8 MB

// ---------------- PTX helpers (sm_80-compatible only) ----------------
__device__ __forceinline__ uint32_t smem_u32(const void* p) {
    uint32_t a;
    asm("{ .reg .u64 t; cvta.to.shared.u64 t, %1; cvt.u32.u64 %0, t; }"
        : "=r"(a) : "l"(p));
    return a;
}
__device__ __forceinline__ void ldsm_x4(uint32_t* r, uint32_t a) {
    asm volatile("ldmatrix.sync.aligned.m8n8.x4.shared.b16 {%0,%1,%2,%3}, [%4];"
                 : "=r"(r[0]), "=r"(r[1]), "=r"(r[2]), "=r"(r[3]) : "r"(a));
}
__device__ __forceinline__ void mma16816h(float* d, const uint32_t* a,
                                          const uint32_t* b) {
    asm volatile(
        "mma.sync.aligned.m16n8k16.row.col.f32.f16.f16.f32 "
        "{%0,%1,%2,%3}, {%4,%5,%6,%7}, {%8,%9}, {%0,%1,%2,%3};"
        : "+f"(d[0]), "+f"(d[1]), "+f"(d[2]), "+f"(d[3])
        : "r"(a[0]), "r"(a[1]), "r"(a[2]), "r"(a[3]), "r"(b[0]), "r"(b[1]));
}
__device__ __forceinline__ void cpasync16(uint32_t dst, const void* src) {
    asm volatile("cp.async.cg.shared.global [%0], [%1], 16;"
                 :: "r"(dst), "l"(src) : "memory");
}

// ---------------------------------------------------------------------------
// Kernel I: input fp32 -> fp16 hi/lo split (streaming)
// ---------------------------------------------------------------------------
__global__ __launch_bounds__(256) void k_iconv(const float* __restrict__ inp) {
    size_t off = ((size_t)blockIdx.x * 256 + threadIdx.x) * 8;
    float4 v0 = *(const float4*)(inp + off);
    float4 v1 = *(const float4*)(inp + off + 4);
    __half h[8], l[8];
    float vv[8] = {v0.x, v0.y, v0.z, v0.w, v1.x, v1.y, v1.z, v1.w};
#pragma unroll
    for (int i = 0; i < 8; i++) {
        h[i] = __float2half_rn(vv[i]);
        l[i] = __float2half_rn(vv[i] - __half2float(h[i]));
    }
    *(uint4*)(g_i_hi + off) = *(uint4*)h;
    *(uint4*)(g_i_lo + off) = *(uint4*)l;
}

// ---------------------------------------------------------------------------
// Kernel W: W [k][f] fp32 -> wT hi/lo [f][k] fp16 (tiny)
// ---------------------------------------------------------------------------
__global__ __launch_bounds__(256) void k_wconv(const float* __restrict__ W) {
    int idx = blockIdx.x * 256 + threadIdx.x;   // 8192 total
    int f = (idx * 4) >> 8, k0 = (idx * 4) & 255;
    __half h[4], l[4];
#pragma unroll
    for (int i = 0; i < 4; i++) {
        float v = W[(size_t)(k0 + i) * FOUT + f];
        h[i] = __float2half_rn(v);
        l[i] = __float2half_rn(v - __half2float(h[i]));
    }
    *(uint2*)(g_wT_hi + (size_t)f * FIN + k0) = *(uint2*)h;
    *(uint2*)(g_wT_lo + (size_t)f * FIN + k0) = *(uint2*)l;
}

// ---------------------------------------------------------------------------
// Kernel G: h = input @ W via 3-term fp16 HMMA; fused epilogue writes
// g_hT_hi/lo (transposed, via smem bounce) and g_f1/g_f2. No fp32 h at all.
// CTA = 128 m x 128 f; warps 2x4 (64x32 tiles); K chunks of 32, 3 buffers.
// ---------------------------------------------------------------------------
#define SG_BUF   32768                 // per buffer: A 16KB + B 16KB
#define SG_TOTAL (3 * SG_BUF)          // 98,304 B

__global__ __launch_bounds__(256, 2) void k_gemm_h_tc(const float* __restrict__ a1,
                                                      const float* __restrict__ a2) {
    extern __shared__ char smem[];
    const uint32_t sb = smem_u32(smem);
    const int tid = threadIdx.x;
    const int w = tid >> 5, lane = tid & 31;
    const int gid = lane >> 2, qc = lane & 3;
    const int m0 = blockIdx.x * 128;
    const int b = m0 >> 11, n0g = m0 & 2047;
    const int m0w = (w >> 2) * 64, n0 = (w & 3) * 32;

    const uint32_t xm = (uint32_t)((lane & 7) << 4);
    const uint32_t arow_off = (uint32_t)(m0w + (lane & 15)) * 128;
    const uint32_t brow_off = 16384u + (uint32_t)(n0 + ((lane & 16) >> 1) + (lane & 7)) * 128;
    const uint32_t acb0 = (uint32_t)(lane & 16);
    const uint32_t bcb0 = (uint32_t)((lane & 8) << 1);

    float acc[16][4];
#pragma unroll
    for (int t = 0; t < 16; t++)
#pragma unroll
        for (int q = 0; q < 4; q++) acc[t][q] = 0.f;

    auto issue = [&](int cj) {
        const uint32_t bufb = (uint32_t)(cj % 3) * SG_BUF;
        const int kk = cj * 32;
#pragma unroll
        for (int k = 0; k < 4; k++) {   // A tile (input)
            int idx = tid + k * 256;
            int row = idx >> 3, jg = idx & 7;
            uint32_t c = (uint32_t)jg * 16;
            uint32_t dst = sb + bufb + (uint32_t)row * 128 + (c ^ ((uint32_t)(row & 7) << 4));
            const __half* src = (jg < 4 ? g_i_hi : g_i_lo) +
                                (size_t)(m0 + row) * FIN + kk + (jg & 3) * 8;
            cpasync16(dst, src);
        }
#pragma unroll
        for (int k = 0; k < 4; k++) {   // B tile (wT)
            int idx = tid + k * 256;
            int row = idx >> 3, jg = idx & 7;
            uint32_t c = (uint32_t)jg * 16;
            uint32_t dst = sb + bufb + 16384u + (uint32_t)row * 128 + (c ^ ((uint32_t)(row & 7) << 4));
            const __half* src = (jg < 4 ? g_wT_hi : g_wT_lo) +
                                (size_t)row * FIN + kk + (jg & 3) * 8;
            cpasync16(dst, src);
        }
        asm volatile("cp.async.commit_group;" ::: "memory");
    };

    issue(0);
    issue(1);

    for (int c = 0; c < NCHG; c++) {
        if (c + 2 < NCHG) {
            asm volatile("cp.async.wait_group 1;" ::: "memory");
        } else {
            asm volatile("cp.async.wait_group 0;" ::: "memory");
        }
        __syncthreads();
        if (c + 2 < NCHG) issue(c + 2);

        const uint32_t bufb = sb + (uint32_t)(c % 3) * SG_BUF;
#pragma unroll
        for (int ks = 0; ks < 2; ks++) {
            const uint32_t cbh = (uint32_t)ks * 32;
            const uint32_t bcoh = (cbh + bcb0) ^ xm;
            const uint32_t bcol = (cbh + 64 + bcb0) ^ xm;
            const uint32_t acoh = (cbh + acb0) ^ xm;
            const uint32_t acol = (cbh + 64 + acb0) ^ xm;
            uint32_t bh[8], bl[8];
            ldsm_x4(bh,     bufb + brow_off + bcoh);
            ldsm_x4(bh + 4, bufb + brow_off + 2048 + bcoh);
            ldsm_x4(bl,     bufb + brow_off + bcol);
            ldsm_x4(bl + 4, bufb + brow_off + 2048 + bcol);
#pragma unroll
            for (int mt = 0; mt < 4; mt++) {
                uint32_t ah[4], al[4];
                ldsm_x4(ah, bufb + arow_off + mt * 2048 + acoh);
                ldsm_x4(al, bufb + arow_off + mt * 2048 + acol);
#pragma unroll
                for (int nt = 0; nt < 4; nt++) {
                    mma16816h(acc[mt * 4 + nt], ah, bh + nt * 2);   // ihi*whi
                    mma16816h(acc[mt * 4 + nt], ah, bl + nt * 2);   // ihi*wlo
                    mma16816h(acc[mt * 4 + nt], al, bh + nt * 2);   // ilo*whi
                }
            }
        }
    }
    __syncthreads();   // all ldsm reads done; smem free for epilogue reuse

    // ---- f1/f2 partials from fp32 accumulators ----
    float p1[8], p2[8];
#pragma unroll
    for (int i = 0; i < 8; i++) { p1[i] = 0.f; p2[i] = 0.f; }
#pragma unroll
    for (int mt = 0; mt < 4; mt++)
#pragma unroll
        for (int nt = 0; nt < 4; nt++) {
            int col = n0 + nt * 8 + 2 * qc;
            float a10 = a1[col], a11 = a1[col + 1];
            float a20 = a2[col], a21 = a2[col + 1];
            const float* a4 = acc[mt * 4 + nt];
            p1[mt * 2]     += a4[0] * a10 + a4[1] * a11;
            p1[mt * 2 + 1] += a4[2] * a10 + a4[3] * a11;
            p2[mt * 2]     += a4[0] * a20 + a4[1] * a21;
            p2[mt * 2 + 1] += a4[2] * a20 + a4[3] * a21;
        }
#pragma unroll
    for (int i = 0; i < 8; i++) {
        p1[i] += __shfl_xor_sync(0xffffffffu, p1[i], 1);
        p1[i] += __shfl_xor_sync(0xffffffffu, p1[i], 2);
        p2[i] += __shfl_xor_sync(0xffffffffu, p2[i], 1);
        p2[i] += __shfl_xor_sync(0xffffffffu, p2[i], 2);
    }
    float* sf1 = (float*)smem;              // [128][4]
    float* sf2 = (float*)(smem + 2048);
    if (qc == 0) {
#pragma unroll
        for (int mt = 0; mt < 4; mt++)
#pragma unroll
            for (int rr = 0; rr < 2; rr++) {
                int rl = m0w + mt * 16 + rr * 8 + gid;
                sf1[rl * 4 + (w & 3)] = p1[mt * 2 + rr];
                sf2[rl * 4 + (w & 3)] = p2[mt * 2 + rr];
            }
    }

    // ---- hT transpose bounce (hi/lo), pitch 136 halfs (272B, 16B-aligned) ----
    __half* sth = (__half*)(smem + 4096);
    __half* stl = (__half*)(smem + 4096 + 34816);
#pragma unroll
    for (int mt = 0; mt < 4; mt++)
#pragma unroll
        for (int nt = 0; nt < 4; nt++) {
            int col = n0 + nt * 8 + 2 * qc;
            int rl = m0w + mt * 16 + gid;
            const float* a4 = acc[mt * 4 + nt];
#pragma unroll
            for (int q = 0; q < 4; q++) {
                int cc = col + (q & 1);
                int rr = rl + (q >> 1) * 8;
                __half hv = __float2half_rn(a4[q]);
                __half lv = __float2half_rn(a4[q] - __half2float(hv));
                sth[cc * 136 + rr] = hv;
                stl[cc * 136 + rr] = lv;
            }
        }
    __syncthreads();

    if (tid < 128) {
        float s1 = sf1[tid * 4] + sf1[tid * 4 + 1] + sf1[tid * 4 + 2] + sf1[tid * 4 + 3];
        float s2 = sf2[tid * 4] + sf2[tid * 4 + 1] + sf2[tid * 4 + 2] + sf2[tid * 4 + 3];
        g_f1[m0 + tid] = s1;
        g_f2[m0 + tid] = s2;
    }
    {
        // FIXED: copy the full 64-half slice (8 x uint4, stride 8 halfs).
        int f = tid >> 1, c0 = (tid & 1) * 64;
        size_t gb = ((size_t)(b * FOUT + f)) * N_ + n0g + c0;
#pragma unroll
        for (int q = 0; q < 8; q++) {
            *(uint4*)&g_hT_hi[gb + q * 8] = *(uint4*)&sth[f * 136 + c0 + q * 8];
            *(uint4*)&g_hT_lo[gb + q * 8] = *(uint4*)&stl[f * 136 + c0 + q * 8];
        }
    }
}

// ---------------------------------------------------------------------------
// Kernel B2: per-batch max of f2 (for the softmax shift bound)
// ---------------------------------------------------------------------------
__global__ __launch_bounds__(256) void k_f2max() {
    const int b = blockIdx.x, tid = threadIdx.x;
    float m = -1e30f;
    for (int i = tid; i < N_; i += 256) m = fmaxf(m, g_f2[b * N_ + i]);
#pragma unroll
    for (int o = 16; o; o >>= 1) m = fmaxf(m, __shfl_xor_sync(0xffffffffu, m, o));
    __shared__ float s[8];
    if ((tid & 31) == 0) s[tid >> 5] = m;
    __syncthreads();
    if (tid < 8) {
        float mm = s[tid];
#pragma unroll
        for (int o = 4; o; o >>= 1) mm = fmaxf(mm, __shfl_xor_sync(0xffu, mm, o));
        if (tid == 0) g_f2max[b] = mm;
    }
}

// ---------------------------------------------------------------------------
// Kernel D: chunk-pipelined HMMA attention, fp16 2-term max-shifted.
// (unchanged from the 217.6us best)
// ---------------------------------------------------------------------------
#define SA_DEN   0
#define SA_P     512
#define SA_H     (SA_P + 16384)
#define SA_TOTAL (SA_H + 32768)

__global__ __launch_bounds__(256, 2) void k_attn_mma(const int* __restrict__ adj,
                                                     float* __restrict__ out) {
    extern __shared__ char smem[];
    const uint32_t sb = smem_u32(smem);
    const int tid = threadIdx.x;
    const int w = tid >> 5, lane = tid & 31;
    const int b = blockIdx.y, i0 = blockIdx.x * 128;

    const int pi = tid >> 1;
    const int pj = (tid & 1) * 16;
    const float f1v = g_f1[b * N_ + i0 + pi];
    const float mf2 = g_f2max[b];
    const float tM  = f1v + mf2;
    const float Mi  = fmaxf(tM, 0.2f * tM);
    const float* f2b = g_f2 + b * N_;
    const int* adjr = adj + (size_t)(b * N_ + i0 + pi) * N_;
    const uint32_t prow = (uint32_t)pi * 128;
    const uint32_t pxm = (uint32_t)((pi & 7) << 4);
    float den = 0.f;

    const int m0 = (w >> 2) * 64, n0 = (w & 3) * 32;
    const uint32_t xm = (uint32_t)((lane & 7) << 4);
    const uint32_t arow = sb + SA_P + (uint32_t)(m0 + (lane & 15)) * 128;
    const uint32_t brow0 = sb + SA_H +
        (uint32_t)(n0 + ((lane & 16) >> 1) + (lane & 7)) * 128;
    const uint32_t acb0 = (uint32_t)(lane & 16);
    const uint32_t bcb0 = (uint32_t)((lane & 8) << 1);

    float acc[16][4];
#pragma unroll
    for (int t = 0; t < 16; t++)
#pragma unroll
        for (int q = 0; q < 4; q++) acc[t][q] = 0.f;

    auto issueH = [&](int cj) {
        const int jj = cj * JC;
        const uint32_t pb64 = (uint32_t)(cj & 1) * 64;
#pragma unroll
        for (int k = 0; k < 4; k++) {
            int idx = tid + k * 256;
            int bufl = idx >> 9;
            int rem = idx & 511;
            int f = rem >> 2, jg = rem & 3;
            uint32_t dst = sb + SA_H + bufl * 16384 + (uint32_t)f * 128 +
                           ((pb64 + (uint32_t)jg * 16) ^ ((uint32_t)(f & 7) << 4));
            const __half* src =
                (bufl ? g_hT_lo : g_hT_hi) + ((size_t)(b * FOUT + f)) * N_ + jj + jg * 8;
            cpasync16(dst, src);
        }
        asm volatile("cp.async.commit_group;" ::: "memory");
    };

    auto genP = [&](int cj, const int4* av) {
        const int jj = cj * JC + pj;
        const uint32_t pb64 = (uint32_t)(cj & 1) * 64;
#pragma unroll
        for (int q = 0; q < 4; q++) {
            float4 f2v = *(const float4*)&f2b[jj + q * 4];
            float e0 = f1v + f2v.x, e1 = f1v + f2v.y;
            float e2 = f1v + f2v.z, e3 = f1v + f2v.w;
            e0 = fmaxf(e0, 0.2f * e0) - Mi;
            e1 = fmaxf(e1, 0.2f * e1) - Mi;
            e2 = fmaxf(e2, 0.2f * e2) - Mi;
            e3 = fmaxf(e3, 0.2f * e3) - Mi;
            float w0 = (av[q].x > 0) ? __expf(e0) : 0.f;
            float w1 = (av[q].y > 0) ? __expf(e1) : 0.f;
            float w2 = (av[q].z > 0) ? __expf(e2) : 0.f;
            float w3 = (av[q].w > 0) ? __expf(e3) : 0.f;
            den += (w0 + w1) + (w2 + w3);
            __half2 p01 = __floats2half2_rn(w0, w1);
            __half2 p23 = __floats2half2_rn(w2, w3);
            uint32_t off = prow + ((pb64 + (uint32_t)(pj + q * 4) * 2) ^ pxm);
            unsigned long long vhi = (unsigned long long)*(uint32_t*)&p01 |
                                     ((unsigned long long)*(uint32_t*)&p23 << 32);
            *(unsigned long long*)(smem + SA_P + off) = vhi;
        }
    };

    int4 apre[4];
#pragma unroll
    for (int q = 0; q < 4; q++)
        apre[q] = *(const int4*)(adjr + pj + q * 4);
    issueH(0);
    genP(0, apre);
#pragma unroll
    for (int q = 0; q < 4; q++)
        apre[q] = *(const int4*)(adjr + JC + pj + q * 4);

    for (int c = 0; c < NCH; c++) {
        const uint32_t pb64 = (uint32_t)(c & 1) * 64;

        asm volatile("cp.async.wait_group 0;" ::: "memory");
        __syncthreads();

        if (c + 1 < NCH) issueH(c + 1);

#pragma unroll
        for (int ks = 0; ks < 2; ks++) {
            const uint32_t cb = pb64 + (uint32_t)ks * 32;
            const uint32_t bco = (cb + bcb0) ^ xm;
            const uint32_t aco = (cb + acb0) ^ xm;
            uint32_t bh[8], bl[8];
            ldsm_x4(bh,     brow0 + bco);
            ldsm_x4(bh + 4, brow0 + 2048 + bco);
            ldsm_x4(bl,     brow0 + 16384 + bco);
            ldsm_x4(bl + 4, brow0 + 16384 + 2048 + bco);
            uint32_t ah[2][4];
#pragma unroll
            for (int mt = 0; mt < 4; mt++) {
                uint32_t* ahp = ah[mt & 1];
                ldsm_x4(ahp, arow + mt * 2048 + aco);
#pragma unroll
                for (int nt = 0; nt < 4; nt++) {
                    mma16816h(acc[mt * 4 + nt], ahp, bh + nt * 2);
                    mma16816h(acc[mt * 4 + nt], ahp, bl + nt * 2);
                }
            }
        }

        if (c + 1 < NCH) {
            genP(c + 1, apre);
            int cn = (c + 2 < NCH) ? (c + 2) : (NCH - 1);
#pragma unroll
            for (int q = 0; q < 4; q++)
                apre[q] = *(const int4*)(adjr + cn * JC + pj + q * 4);
        }
    }

    den += __shfl_xor_sync(0xffffffffu, den, 1);
    __syncthreads();
    if ((tid & 1) == 0) ((float*)(smem + SA_DEN))[pi] = den;
    __syncthreads();

    const float* dsm = (const float*)(smem + SA_DEN);
    const int gid = lane >> 2, qc = lane & 3;
#pragma unroll
    for (int mt = 0; mt < 4; mt++) {
        int r0 = m0 + mt * 16 + gid;
        float d0 = dsm[r0], d1 = dsm[r0 + 8];
        float inv0 = (d0 > 0.f) ? (1.f / d0) : 0.f;
        float inv1 = (d1 > 0.f) ? (1.f / d1) : 0.f;
#pragma unroll
        for (int nt = 0; nt < 4; nt++) {
            int col = n0 + nt * 8 + 2 * qc;
            const float* a4 = acc[mt * 4 + nt];
            float v;
            float2 o;
            v = a4[0] * inv0; o.x = (v > 0.f) ? v : expm1f(v);
            v = a4[1] * inv0; o.y = (v > 0.f) ? v : expm1f(v);
            *(float2*)&out[((size_t)(b * N_ + i0 + r0)) * FOUT + col] = o;
            v = a4[2] * inv1; o.x = (v > 0.f) ? v : expm1f(v);
            v = a4[3] * inv1; o.y = (v > 0.f) ? v : expm1f(v);
            *(float2*)&out[((size_t)(b * N_ + i0 + r0 + 8)) * FOUT + col] = o;
        }
    }
}

// ---------------------------------------------------------------------------
extern "C" void kernel_launch(void* const* d_in, const int* in_sizes, int n_in,
                              void* d_out, int out_size) {
    const float* inp = (const float*)d_in[0];
    const int*   adj = (const int*)d_in[1];
    const float* W   = (const float*)d_in[2];
    const float* a1  = (const float*)d_in[3];
    const float* a2  = (const float*)d_in[4];
    float* out = (float*)d_out;

    cudaFuncSetAttribute(k_gemm_h_tc, cudaFuncAttributeMaxDynamicSharedMemorySize,
                         SG_TOTAL);
    cudaFuncSetAttribute(k_attn_mma, cudaFuncAttributeMaxDynamicSharedMemorySize,
                         SA_TOTAL);

    k_iconv<<<(int)((size_t)MTOT * FIN / (256 * 8)), 256>>>(inp);
    k_wconv<<<32, 256>>>(W);
    k_gemm_h_tc<<<MTOT / 128, 256, SG_TOTAL>>>(a1, a2);
    k_f2max<<<B_, 256>>>();
    dim3 gattn(N_ / 128, B_);
    k_attn_mma<<<gattn, 256, SA_TOTAL>>>(adj, out);
}

// round 17
// speedup vs baseline: 2.3245x; 1.2618x over previous
#include <cuda_runtime.h>
#include <cuda_bf16.h>
#include <cuda_fp16.h>
#include <cstdint>
#include <cstddef>

#define B_    16
#define N_    2048
#define FIN   256
#define FOUT  128
#define MTOT  (B_ * N_)
#define JC    32
#define NCH   (N_ / JC)
#define NCHG  (FIN / 32)

// ---------------- device scratch (no allocation allowed) ----------------
__device__ float g_f1[MTOT];
__device__ float g_f2[MTOT];
__device__ __half g_i_hi[(size_t)MTOT * FIN];           // 16 MB [m][k]
__device__ __half g_i_lo[(size_t)MTOT * FIN];           // 16 MB
__device__ __half g_wT_hi[(size_t)FOUT * FIN];          // 64 KB [f][k]
__device__ __half g_wT_lo[(size_t)FOUT * FIN];
__device__ __half g_hT_hi[(size_t)B_ * FOUT * N_];      // 8 MB  [b][f][n]

// ---------------- PTX helpers (sm_80-compatible only) ----------------
__device__ __forceinline__ uint32_t smem_u32(const void* p) {
    uint32_t a;
    asm("{ .reg .u64 t; cvta.to.shared.u64 t, %1; cvt.u32.u64 %0, t; }"
        : "=r"(a) : "l"(p));
    return a;
}
__device__ __forceinline__ void ldsm_x4(uint32_t* r, uint32_t a) {
    asm volatile("ldmatrix.sync.aligned.m8n8.x4.shared.b16 {%0,%1,%2,%3}, [%4];"
                 : "=r"(r[0]), "=r"(r[1]), "=r"(r[2]), "=r"(r[3]) : "r"(a));
}
__device__ __forceinline__ void mma16816h(float* d, const uint32_t* a,
                                          const uint32_t* b) {
    asm volatile(
        "mma.sync.aligned.m16n8k16.row.col.f32.f16.f16.f32 "
        "{%0,%1,%2,%3}, {%4,%5,%6,%7}, {%8,%9}, {%0,%1,%2,%3};"
        : "+f"(d[0]), "+f"(d[1]), "+f"(d[2]), "+f"(d[3])
        : "r"(a[0]), "r"(a[1]), "r"(a[2]), "r"(a[3]), "r"(b[0]), "r"(b[1]));
}
__device__ __forceinline__ void cpasync16(uint32_t dst, const void* src) {
    asm volatile("cp.async.cg.shared.global [%0], [%1], 16;"
                 :: "r"(dst), "l"(src) : "memory");
}

// ---------------------------------------------------------------------------
// Kernel I: input fp32 -> fp16 hi/lo split (streaming)
// ---------------------------------------------------------------------------
__global__ __launch_bounds__(256) void k_iconv(const float* __restrict__ inp) {
    size_t off = ((size_t)blockIdx.x * 256 + threadIdx.x) * 8;
    float4 v0 = *(const float4*)(inp + off);
    float4 v1 = *(const float4*)(inp + off + 4);
    __half h[8], l[8];
    float vv[8] = {v0.x, v0.y, v0.z, v0.w, v1.x, v1.y, v1.z, v1.w};
#pragma unroll
    for (int i = 0; i < 8; i++) {
        h[i] = __float2half_rn(vv[i]);
        l[i] = __float2half_rn(vv[i] - __half2float(h[i]));
    }
    *(uint4*)(g_i_hi + off) = *(uint4*)h;
    *(uint4*)(g_i_lo + off) = *(uint4*)l;
}

// ---------------------------------------------------------------------------
// Kernel W: W [k][f] fp32 -> wT hi/lo [f][k] fp16 (tiny)
// ---------------------------------------------------------------------------
__global__ __launch_bounds__(256) void k_wconv(const float* __restrict__ W) {
    int idx = blockIdx.x * 256 + threadIdx.x;   // 8192 total
    int f = (idx * 4) >> 8, k0 = (idx * 4) & 255;
    __half h[4], l[4];
#pragma unroll
    for (int i = 0; i < 4; i++) {
        float v = W[(size_t)(k0 + i) * FOUT + f];
        h[i] = __float2half_rn(v);
        l[i] = __float2half_rn(v - __half2float(h[i]));
    }
    *(uint2*)(g_wT_hi + (size_t)f * FIN + k0) = *(uint2*)h;
    *(uint2*)(g_wT_lo + (size_t)f * FIN + k0) = *(uint2*)l;
}

// ---------------------------------------------------------------------------
// Kernel G: h = input @ W via 3-term fp16 HMMA; fused epilogue writes
// g_hT_hi (transposed, via smem bounce) and g_f1/g_f2. No fp32 h at all.
// CTA = 128 m x 128 f; warps 2x4 (64x32 tiles); K chunks of 32, 3 buffers.
// ---------------------------------------------------------------------------
#define SG_BUF   32768                 // per buffer: A 16KB + B 16KB
#define SG_TOTAL (3 * SG_BUF)          // 98,304 B

__global__ __launch_bounds__(256, 2) void k_gemm_h_tc(const float* __restrict__ a1,
                                                      const float* __restrict__ a2) {
    extern __shared__ char smem[];
    const uint32_t sb = smem_u32(smem);
    const int tid = threadIdx.x;
    const int w = tid >> 5, lane = tid & 31;
    const int gid = lane >> 2, qc = lane & 3;
    const int m0 = blockIdx.x * 128;
    const int b = m0 >> 11, n0g = m0 & 2047;
    const int m0w = (w >> 2) * 64, n0 = (w & 3) * 32;

    const uint32_t xm = (uint32_t)((lane & 7) << 4);
    const uint32_t arow_off = (uint32_t)(m0w + (lane & 15)) * 128;
    const uint32_t brow_off = 16384u + (uint32_t)(n0 + ((lane & 16) >> 1) + (lane & 7)) * 128;
    const uint32_t acb0 = (uint32_t)(lane & 16);
    const uint32_t bcb0 = (uint32_t)((lane & 8) << 1);

    float acc[16][4];
#pragma unroll
    for (int t = 0; t < 16; t++)
#pragma unroll
        for (int q = 0; q < 4; q++) acc[t][q] = 0.f;

    auto issue = [&](int cj) {
        const uint32_t bufb = (uint32_t)(cj % 3) * SG_BUF;
        const int kk = cj * 32;
#pragma unroll
        for (int k = 0; k < 4; k++) {   // A tile (input)
            int idx = tid + k * 256;
            int row = idx >> 3, jg = idx & 7;
            uint32_t c = (uint32_t)jg * 16;
            uint32_t dst = sb + bufb + (uint32_t)row * 128 + (c ^ ((uint32_t)(row & 7) << 4));
            const __half* src = (jg < 4 ? g_i_hi : g_i_lo) +
                                (size_t)(m0 + row) * FIN + kk + (jg & 3) * 8;
            cpasync16(dst, src);
        }
#pragma unroll
        for (int k = 0; k < 4; k++) {   // B tile (wT)
            int idx = tid + k * 256;
            int row = idx >> 3, jg = idx & 7;
            uint32_t c = (uint32_t)jg * 16;
            uint32_t dst = sb + bufb + 16384u + (uint32_t)row * 128 + (c ^ ((uint32_t)(row & 7) << 4));
            const __half* src = (jg < 4 ? g_wT_hi : g_wT_lo) +
                                (size_t)row * FIN + kk + (jg & 3) * 8;
            cpasync16(dst, src);
        }
        asm volatile("cp.async.commit_group;" ::: "memory");
    };

    issue(0);
    issue(1);

    for (int c = 0; c < NCHG; c++) {
        if (c + 2 < NCHG) {
            asm volatile("cp.async.wait_group 1;" ::: "memory");
        } else {
            asm volatile("cp.async.wait_group 0;" ::: "memory");
        }
        __syncthreads();
        if (c + 2 < NCHG) issue(c + 2);

        const uint32_t bufb = sb + (uint32_t)(c % 3) * SG_BUF;
#pragma unroll
        for (int ks = 0; ks < 2; ks++) {
            const uint32_t cbh = (uint32_t)ks * 32;
            const uint32_t bcoh = (cbh + bcb0) ^ xm;
            const uint32_t bcol = (cbh + 64 + bcb0) ^ xm;
            const uint32_t acoh = (cbh + acb0) ^ xm;
            const uint32_t acol = (cbh + 64 + acb0) ^ xm;
            uint32_t bh[8], bl[8];
            ldsm_x4(bh,     bufb + brow_off + bcoh);
            ldsm_x4(bh + 4, bufb + brow_off + 2048 + bcoh);
            ldsm_x4(bl,     bufb + brow_off + bcol);
            ldsm_x4(bl + 4, bufb + brow_off + 2048 + bcol);
#pragma unroll
            for (int mt = 0; mt < 4; mt++) {
                uint32_t ah[4], al[4];
                ldsm_x4(ah, bufb + arow_off + mt * 2048 + acoh);
                ldsm_x4(al, bufb + arow_off + mt * 2048 + acol);
#pragma unroll
                for (int nt = 0; nt < 4; nt++) {
                    mma16816h(acc[mt * 4 + nt], ah, bh + nt * 2);   // ihi*whi
                    mma16816h(acc[mt * 4 + nt], ah, bl + nt * 2);   // ihi*wlo
                    mma16816h(acc[mt * 4 + nt], al, bh + nt * 2);   // ilo*whi
                }
            }
        }
    }
    __syncthreads();   // all ldsm reads done; smem free for epilogue reuse

    // ---- f1/f2 partials from fp32 accumulators ----
    float p1[8], p2[8];
#pragma unroll
    for (int i = 0; i < 8; i++) { p1[i] = 0.f; p2[i] = 0.f; }
#pragma unroll
    for (int mt = 0; mt < 4; mt++)
#pragma unroll
        for (int nt = 0; nt < 4; nt++) {
            int col = n0 + nt * 8 + 2 * qc;
            float a10 = a1[col], a11 = a1[col + 1];
            float a20 = a2[col], a21 = a2[col + 1];
            const float* a4 = acc[mt * 4 + nt];
            p1[mt * 2]     += a4[0] * a10 + a4[1] * a11;
            p1[mt * 2 + 1] += a4[2] * a10 + a4[3] * a11;
            p2[mt * 2]     += a4[0] * a20 + a4[1] * a21;
            p2[mt * 2 + 1] += a4[2] * a20 + a4[3] * a21;
        }
#pragma unroll
    for (int i = 0; i < 8; i++) {
        p1[i] += __shfl_xor_sync(0xffffffffu, p1[i], 1);
        p1[i] += __shfl_xor_sync(0xffffffffu, p1[i], 2);
        p2[i] += __shfl_xor_sync(0xffffffffu, p2[i], 1);
        p2[i] += __shfl_xor_sync(0xffffffffu, p2[i], 2);
    }
    float* sf1 = (float*)smem;              // [128][4]
    float* sf2 = (float*)(smem + 2048);
    if (qc == 0) {
#pragma unroll
        for (int mt = 0; mt < 4; mt++)
#pragma unroll
            for (int rr = 0; rr < 2; rr++) {
                int rl = m0w + mt * 16 + rr * 8 + gid;
                sf1[rl * 4 + (w & 3)] = p1[mt * 2 + rr];
                sf2[rl * 4 + (w & 3)] = p2[mt * 2 + rr];
            }
    }

    // ---- hT transpose bounce (hi only), pitch 136 halfs (272B, 16B-aligned) ----
    __half* sth = (__half*)(smem + 4096);
#pragma unroll
    for (int mt = 0; mt < 4; mt++)
#pragma unroll
        for (int nt = 0; nt < 4; nt++) {
            int col = n0 + nt * 8 + 2 * qc;
            int rl = m0w + mt * 16 + gid;
            const float* a4 = acc[mt * 4 + nt];
#pragma unroll
            for (int q = 0; q < 4; q++) {
                int cc = col + (q & 1);
                int rr = rl + (q >> 1) * 8;
                sth[cc * 136 + rr] = __float2half_rn(a4[q]);
            }
        }
    __syncthreads();

    if (tid < 128) {
        float s1 = sf1[tid * 4] + sf1[tid * 4 + 1] + sf1[tid * 4 + 2] + sf1[tid * 4 + 3];
        float s2 = sf2[tid * 4] + sf2[tid * 4 + 1] + sf2[tid * 4 + 2] + sf2[tid * 4 + 3];
        g_f1[m0 + tid] = s1;
        g_f2[m0 + tid] = s2;
    }
    {
        // full 64-half slice per thread (8 x uint4, stride 8 halfs)
        int f = tid >> 1, c0 = (tid & 1) * 64;
        size_t gb = ((size_t)(b * FOUT + f)) * N_ + n0g + c0;
#pragma unroll
        for (int q = 0; q < 8; q++)
            *(uint4*)&g_hT_hi[gb + q * 8] = *(uint4*)&sth[f * 136 + c0 + q * 8];
    }
}

// ---------------------------------------------------------------------------
// Kernel D: chunk-pipelined HMMA attention, fp16 single-term max-shifted.
// w = exp(leaky(f1+f2) - M_i) in (0,1] -> fp16 P; H fp16 hi only.
// Per-CTA f2max reduction at startup (replaces standalone kernel).
// ---------------------------------------------------------------------------
#define SA_DEN   0
#define SA_P     512
#define SA_H     (SA_P + 16384)
#define SA_TOTAL (SA_H + 16384)        // 33,280 B

__global__ __launch_bounds__(256, 2) void k_attn_mma(const int* __restrict__ adj,
                                                     float* __restrict__ out) {
    extern __shared__ char smem[];
    const uint32_t sb = smem_u32(smem);
    const int tid = threadIdx.x;
    const int w = tid >> 5, lane = tid & 31;
    const int b = blockIdx.y, i0 = blockIdx.x * 128;

    const int pi = tid >> 1;
    const int pj = (tid & 1) * 16;
    const float* f2b = g_f2 + b * N_;
    const int* adjr = adj + (size_t)(b * N_ + i0 + pi) * N_;
    const uint32_t prow = (uint32_t)pi * 128;
    const uint32_t pxm = (uint32_t)((pi & 7) << 4);
    float den = 0.f;

    const int m0 = (w >> 2) * 64, n0 = (w & 3) * 32;
    const uint32_t xm = (uint32_t)((lane & 7) << 4);
    const uint32_t arow = sb + SA_P + (uint32_t)(m0 + (lane & 15)) * 128;
    const uint32_t brow0 = sb + SA_H +
        (uint32_t)(n0 + ((lane & 16) >> 1) + (lane & 7)) * 128;
    const uint32_t acb0 = (uint32_t)(lane & 16);
    const uint32_t bcb0 = (uint32_t)((lane & 8) << 1);

    float acc[16][4];
#pragma unroll
    for (int t = 0; t < 16; t++)
#pragma unroll
        for (int q = 0; q < 4; q++) acc[t][q] = 0.f;

    auto issueH = [&](int cj) {
        const int jj = cj * JC;
        const uint32_t pb64 = (uint32_t)(cj & 1) * 64;
#pragma unroll
        for (int k = 0; k < 2; k++) {
            int idx = tid + k * 256;
            int f = idx >> 2, jg = idx & 3;
            uint32_t dst = sb + SA_H + (uint32_t)f * 128 +
                           ((pb64 + (uint32_t)jg * 16) ^ ((uint32_t)(f & 7) << 4));
            const __half* src =
                g_hT_hi + ((size_t)(b * FOUT + f)) * N_ + jj + jg * 8;
            cpasync16(dst, src);
        }
        asm volatile("cp.async.commit_group;" ::: "memory");
    };

    // ---- H(0) in flight while we reduce f2max ----
    issueH(0);

    // ---- per-CTA max_j f2 (exact; replaces k_f2max kernel) ----
    float lm = -1e30f;
#pragma unroll
    for (int q = 0; q < 8; q++) lm = fmaxf(lm, f2b[tid + q * 256]);
#pragma unroll
    for (int o = 16; o; o >>= 1) lm = fmaxf(lm, __shfl_xor_sync(0xffffffffu, lm, o));
    if (lane == 0) ((float*)(smem + SA_DEN))[w] = lm;
    __syncthreads();
    float mf2 = ((float*)(smem + SA_DEN))[0];
#pragma unroll
    for (int q = 1; q < 8; q++) mf2 = fmaxf(mf2, ((float*)(smem + SA_DEN))[q]);

    const float f1v = g_f1[b * N_ + i0 + pi];
    const float tM  = f1v + mf2;
    const float Mi  = fmaxf(tM, 0.2f * tM);   // leaky(f1 + max f2) >= any masked e

    auto genP = [&](int cj, const int4* av) {
        const int jj = cj * JC + pj;
        const uint32_t pb64 = (uint32_t)(cj & 1) * 64;
#pragma unroll
        for (int q = 0; q < 4; q++) {
            float4 f2v = *(const float4*)&f2b[jj + q * 4];
            float e0 = f1v + f2v.x, e1 = f1v + f2v.y;
            float e2 = f1v + f2v.z, e3 = f1v + f2v.w;
            e0 = fmaxf(e0, 0.2f * e0) - Mi;
            e1 = fmaxf(e1, 0.2f * e1) - Mi;
            e2 = fmaxf(e2, 0.2f * e2) - Mi;
            e3 = fmaxf(e3, 0.2f * e3) - Mi;
            float w0 = (av[q].x > 0) ? __expf(e0) : 0.f;
            float w1 = (av[q].y > 0) ? __expf(e1) : 0.f;
            float w2 = (av[q].z > 0) ? __expf(e2) : 0.f;
            float w3 = (av[q].w > 0) ? __expf(e3) : 0.f;
            den += (w0 + w1) + (w2 + w3);
            __half2 p01 = __floats2half2_rn(w0, w1);
            __half2 p23 = __floats2half2_rn(w2, w3);
            uint32_t off = prow + ((pb64 + (uint32_t)(pj + q * 4) * 2) ^ pxm);
            unsigned long long vhi = (unsigned long long)*(uint32_t*)&p01 |
                                     ((unsigned long long)*(uint32_t*)&p23 << 32);
            *(unsigned long long*)(smem + SA_P + off) = vhi;
        }
    };

    int4 apre[4];
#pragma unroll
    for (int q = 0; q < 4; q++)
        apre[q] = *(const int4*)(adjr + pj + q * 4);
    genP(0, apre);
#pragma unroll
    for (int q = 0; q < 4; q++)
        apre[q] = *(const int4*)(adjr + JC + pj + q * 4);

    for (int c = 0; c < NCH; c++) {
        const uint32_t pb64 = (uint32_t)(c & 1) * 64;

        asm volatile("cp.async.wait_group 0;" ::: "memory");
        __syncthreads();

        if (c + 1 < NCH) issueH(c + 1);

        // ---- MMA(c): single H term ----
#pragma unroll
        for (int ks = 0; ks < 2; ks++) {
            const uint32_t cb = pb64 + (uint32_t)ks * 32;
            const uint32_t bco = (cb + bcb0) ^ xm;
            const uint32_t aco = (cb + acb0) ^ xm;
            uint32_t bh[8];
            ldsm_x4(bh,     brow0 + bco);
            ldsm_x4(bh + 4, brow0 + 2048 + bco);
            uint32_t ah[2][4];
#pragma unroll
            for (int mt = 0; mt < 4; mt++) {
                uint32_t* ahp = ah[mt & 1];
                ldsm_x4(ahp, arow + mt * 2048 + aco);
#pragma unroll
                for (int nt = 0; nt < 4; nt++)
                    mma16816h(acc[mt * 4 + nt], ahp, bh + nt * 2);
            }
        }

        if (c + 1 < NCH) {
            genP(c + 1, apre);
            int cn = (c + 2 < NCH) ? (c + 2) : (NCH - 1);
#pragma unroll
            for (int q = 0; q < 4; q++)
                apre[q] = *(const int4*)(adjr + cn * JC + pj + q * 4);
        }
    }

    den += __shfl_xor_sync(0xffffffffu, den, 1);
    __syncthreads();
    if ((tid & 1) == 0) ((float*)(smem + SA_DEN))[pi] = den;
    __syncthreads();

    const float* dsm = (const float*)(smem + SA_DEN);
    const int gid = lane >> 2, qc = lane & 3;
#pragma unroll
    for (int mt = 0; mt < 4; mt++) {
        int r0 = m0 + mt * 16 + gid;
        float d0 = dsm[r0], d1 = dsm[r0 + 8];
        float inv0 = (d0 > 0.f) ? (1.f / d0) : 0.f;
        float inv1 = (d1 > 0.f) ? (1.f / d1) : 0.f;
#pragma unroll
        for (int nt = 0; nt < 4; nt++) {
            int col = n0 + nt * 8 + 2 * qc;
            const float* a4 = acc[mt * 4 + nt];
            float v;
            float2 o;
            v = a4[0] * inv0; o.x = (v > 0.f) ? v : expm1f(v);
            v = a4[1] * inv0; o.y = (v > 0.f) ? v : expm1f(v);
            *(float2*)&out[((size_t)(b * N_ + i0 + r0)) * FOUT + col] = o;
            v = a4[2] * inv1; o.x = (v > 0.f) ? v : expm1f(v);
            v = a4[3] * inv1; o.y = (v > 0.f) ? v : expm1f(v);
            *(float2*)&out[((size_t)(b * N_ + i0 + r0 + 8)) * FOUT + col] = o;
        }
    }
}

// ---------------------------------------------------------------------------
extern "C" void kernel_launch(void* const* d_in, const int* in_sizes, int n_in,
                              void* d_out, int out_size) {
    const float* inp = (const float*)d_in[0];
    const int*   adj = (const int*)d_in[1];
    const float* W   = (const float*)d_in[2];
    const float* a1  = (const float*)d_in[3];
    const float* a2  = (const float*)d_in[4];
    float* out = (float*)d_out;

    cudaFuncSetAttribute(k_gemm_h_tc, cudaFuncAttributeMaxDynamicSharedMemorySize,
                         SG_TOTAL);
    cudaFuncSetAttribute(k_attn_mma, cudaFuncAttributeMaxDynamicSharedMemorySize,
                         SA_TOTAL);

    k_iconv<<<(int)((size_t)MTOT * FIN / (256 * 8)), 256>>>(inp);
    k_wconv<<<32, 256>>>(W);
    k_gemm_h_tc<<<MTOT / 128, 256, SG_TOTAL>>>(a1, a2);
    dim3 gattn(N_ / 128, B_);
    k_attn_mma<<<gattn, 256, SA_TOTAL>>>(adj, out);
}